// round 10
// baseline (speedup 1.0000x reference)
#include <cuda_runtime.h>
#include <cuda_fp16.h>
#include <cuda_bf16.h>

// out[row[e]] += values[e] * x[col[e]],  row sorted ascending.
// E = 1.6M, N = 100k, D = 64.
//
// fp16 gather table halves L2 gather traffic (410 -> 205 MB); accumulate fp32.
// Kernel 1 (fused prep): convert x->fp16 and build CSR offsets in one launch.
// Kernel 2: one warp per row, quarter-warp (8 lanes) per edge, 4 edges per
//           warp-iteration, unroll 4 -> 4 col loads then 4 gathers front-
//           batched per warp (MLP 4+) to cover ~250cyc L2 latency.

#define N_NODES 100000
#define D_FEAT 64

__device__ int g_row_ptr[N_NODES + 1];
__device__ __align__(256) __half g_x_half[(size_t)N_NODES * D_FEAT];

__global__ void __launch_bounds__(256) fused_prep_kernel(
    const float* __restrict__ x, int n4,          // convert job: n4 = floats/4
    const int* __restrict__ row, int n_edges,     // build job
    int n_nodes, int conv_blocks)
{
    if ((int)blockIdx.x < conv_blocks) {
        int i = blockIdx.x * blockDim.x + threadIdx.x;
        if (i >= n4) return;
        float4 f = __ldg(&((const float4*)x)[i]);
        __half2 h0 = __floats2half2_rn(f.x, f.y);
        __half2 h1 = __floats2half2_rn(f.z, f.w);
        uint2 packed;
        packed.x = *(unsigned*)&h0;
        packed.y = *(unsigned*)&h1;
        ((uint2*)g_x_half)[i] = packed;
    } else {
        int e = (blockIdx.x - conv_blocks) * blockDim.x + threadIdx.x;
        if (e >= n_edges) return;
        int r = row[e];
        int prev = (e == 0) ? -1 : row[e - 1];
        for (int q = prev + 1; q <= r; ++q) g_row_ptr[q] = e;   // lower_bound fill
        if (e == n_edges - 1) {
            for (int q = r + 1; q <= n_nodes; ++q) g_row_ptr[q] = n_edges;
        }
    }
}

__global__ void __launch_bounds__(256) spmm_row_warp_kernel(
    const int* __restrict__ col,
    const float* __restrict__ val,
    float* __restrict__ out,
    int n_nodes)
{
    int r = (blockIdx.x * blockDim.x + threadIdx.x) >> 5;
    if (r >= n_nodes) return;
    int lane = threadIdx.x & 31;
    int grp  = lane >> 3;          // which of 4 edges this lane works on
    int fl   = lane & 7;           // owns fp16 feats [8*fl, 8*fl+8)

    int s = __ldg(&g_row_ptr[r]);
    int e = __ldg(&g_row_ptr[r + 1]);

    const uint4* __restrict__ xq = (const uint4*)g_x_half;  // 8 uint4 per row
    float acc0[8], acc1[8];
    #pragma unroll
    for (int k = 0; k < 8; ++k) { acc0[k] = 0.f; acc1[k] = 0.f; }

    // Two independent accumulator chains (even/odd iterations) + unroll 4:
    // ptxas front-batches 4 col/val loads, then 4 dependent gathers -> MLP 4.
    #pragma unroll 4
    for (int i = s + grp; i < e; i += 4) {
        int   c = __ldg(&col[i]);
        float v = __ldg(&val[i]);
        uint4 raw = __ldg(&xq[(size_t)c * (D_FEAT / 8) + fl]);  // 128B/edge, LDG.128
        const __half2* hp = reinterpret_cast<const __half2*>(&raw);
        float* acc = (((i - s - grp) >> 2) & 1) ? acc1 : acc0;
        #pragma unroll
        for (int k = 0; k < 4; ++k) {
            float2 f = __half22float2(hp[k]);
            acc[2 * k]     = fmaf(v, f.x, acc[2 * k]);
            acc[2 * k + 1] = fmaf(v, f.y, acc[2 * k + 1]);
        }
    }

    #pragma unroll
    for (int k = 0; k < 8; ++k) acc0[k] += acc1[k];

    // reduce the 4 quarter-warp partials (lanes fl, fl+8, fl+16, fl+24)
    #pragma unroll
    for (int k = 0; k < 8; ++k) {
        acc0[k] += __shfl_xor_sync(0xffffffffu, acc0[k], 8);
        acc0[k] += __shfl_xor_sync(0xffffffffu, acc0[k], 16);
    }

    if (grp == 0) {
        float4* out4 = (float4*)out;
        size_t base = (size_t)r * (D_FEAT / 4) + fl * 2;
        out4[base]     = make_float4(acc0[0], acc0[1], acc0[2], acc0[3]);
        out4[base + 1] = make_float4(acc0[4], acc0[5], acc0[6], acc0[7]);
    }
}

extern "C" void kernel_launch(void* const* d_in, const int* in_sizes, int n_in,
                              void* d_out, int out_size) {
    const int*   row = (const int*)d_in[0];
    const int*   col = (const int*)d_in[1];
    const float* val = (const float*)d_in[2];
    const float* x   = (const float*)d_in[3];
    float*       out = (float*)d_out;

    int n_edges = in_sizes[0];
    int n_x     = in_sizes[3];
    int n_nodes = n_x / D_FEAT;

    {
        int threads = 256;
        int n4 = n_x / 4;
        int conv_blocks  = (n4 + threads - 1) / threads;
        int build_blocks = (n_edges + threads - 1) / threads;
        fused_prep_kernel<<<conv_blocks + build_blocks, threads>>>(
            x, n4, row, n_edges, n_nodes, conv_blocks);
    }
    {
        int threads = 256;  // 8 warps/block, 1 row per warp
        long warps = n_nodes;
        int blocks = (int)((warps * 32 + threads - 1) / threads);
        spmm_row_warp_kernel<<<blocks, threads>>>(col, val, out, n_nodes);
    }
}

// round 11
// speedup vs baseline: 1.3893x; 1.3893x over previous
#include <cuda_runtime.h>
#include <cuda_fp16.h>
#include <cuda_bf16.h>

// out[row[e]] += values[e] * x[col[e]],  row sorted ascending.
// E = 1.6M, N = 100k, D = 64.
//
// fp16 gather table halves L2 gather traffic (410 -> 205 MB); accumulate fp32.
// Kernel 1 (fused prep): convert x->fp16 and build CSR offsets in one launch.
// Kernel 2: one warp per row, quarter-warp (8 lanes) per edge, 4 edges per
//           warp-iteration, unroll 4, SINGLE statically-indexed accumulator
//           (R10's dynamic acc select caused reg/ALU blowup — reverted).

#define N_NODES 100000
#define D_FEAT 64

__device__ int g_row_ptr[N_NODES + 1];
__device__ __align__(256) __half g_x_half[(size_t)N_NODES * D_FEAT];

__global__ void __launch_bounds__(256) fused_prep_kernel(
    const float* __restrict__ x, int n4,          // convert job: n4 = floats/4
    const int* __restrict__ row, int n_edges,     // build job
    int n_nodes, int conv_blocks)
{
    if ((int)blockIdx.x < conv_blocks) {
        int i = blockIdx.x * blockDim.x + threadIdx.x;
        if (i >= n4) return;
        float4 f = __ldg(&((const float4*)x)[i]);
        __half2 h0 = __floats2half2_rn(f.x, f.y);
        __half2 h1 = __floats2half2_rn(f.z, f.w);
        uint2 packed;
        packed.x = *(unsigned*)&h0;
        packed.y = *(unsigned*)&h1;
        ((uint2*)g_x_half)[i] = packed;
    } else {
        int e = (blockIdx.x - conv_blocks) * blockDim.x + threadIdx.x;
        if (e >= n_edges) return;
        int r = row[e];
        int prev = (e == 0) ? -1 : row[e - 1];
        for (int q = prev + 1; q <= r; ++q) g_row_ptr[q] = e;   // lower_bound fill
        if (e == n_edges - 1) {
            for (int q = r + 1; q <= n_nodes; ++q) g_row_ptr[q] = n_edges;
        }
    }
}

__global__ void __launch_bounds__(256) spmm_row_warp_kernel(
    const int* __restrict__ col,
    const float* __restrict__ val,
    float* __restrict__ out,
    int n_nodes)
{
    int r = (blockIdx.x * blockDim.x + threadIdx.x) >> 5;
    if (r >= n_nodes) return;
    int lane = threadIdx.x & 31;
    int grp  = lane >> 3;          // which of 4 edges this lane works on
    int fl   = lane & 7;           // owns fp16 feats [8*fl, 8*fl+8)

    int s = __ldg(&g_row_ptr[r]);
    int e = __ldg(&g_row_ptr[r + 1]);

    const uint4* __restrict__ xq = (const uint4*)g_x_half;  // 8 uint4 per row
    float acc[8];
    #pragma unroll
    for (int k = 0; k < 8; ++k) acc[k] = 0.f;

    // Loads are independent of the acc chains: unroll 4 lets ptxas front-batch
    // 4 col/val loads then 4 gathers (MLP 4/warp) to cover ~250cyc L2 latency.
    #pragma unroll 4
    for (int i = s + grp; i < e; i += 4) {
        int   c = __ldg(&col[i]);
        float v = __ldg(&val[i]);
        uint4 raw = __ldg(&xq[(size_t)c * (D_FEAT / 8) + fl]);  // 128B/edge, LDG.128
        const __half2* hp = reinterpret_cast<const __half2*>(&raw);
        #pragma unroll
        for (int k = 0; k < 4; ++k) {
            float2 f = __half22float2(hp[k]);
            acc[2 * k]     = fmaf(v, f.x, acc[2 * k]);
            acc[2 * k + 1] = fmaf(v, f.y, acc[2 * k + 1]);
        }
    }

    // reduce the 4 quarter-warp partials (lanes fl, fl+8, fl+16, fl+24)
    #pragma unroll
    for (int k = 0; k < 8; ++k) {
        acc[k] += __shfl_xor_sync(0xffffffffu, acc[k], 8);
        acc[k] += __shfl_xor_sync(0xffffffffu, acc[k], 16);
    }

    if (grp == 0) {
        float4* out4 = (float4*)out;
        size_t base = (size_t)r * (D_FEAT / 4) + fl * 2;
        out4[base]     = make_float4(acc[0], acc[1], acc[2], acc[3]);
        out4[base + 1] = make_float4(acc[4], acc[5], acc[6], acc[7]);
    }
}

extern "C" void kernel_launch(void* const* d_in, const int* in_sizes, int n_in,
                              void* d_out, int out_size) {
    const int*   row = (const int*)d_in[0];
    const int*   col = (const int*)d_in[1];
    const float* val = (const float*)d_in[2];
    const float* x   = (const float*)d_in[3];
    float*       out = (float*)d_out;

    int n_edges = in_sizes[0];
    int n_x     = in_sizes[3];
    int n_nodes = n_x / D_FEAT;

    {
        int threads = 256;
        int n4 = n_x / 4;
        int conv_blocks  = (n4 + threads - 1) / threads;
        int build_blocks = (n_edges + threads - 1) / threads;
        fused_prep_kernel<<<conv_blocks + build_blocks, threads>>>(
            x, n4, row, n_edges, n_nodes, conv_blocks);
    }
    {
        int threads = 256;  // 8 warps/block, 1 row per warp
        long warps = n_nodes;
        int blocks = (int)((warps * 32 + threads - 1) / threads);
        spmm_row_warp_kernel<<<blocks, threads>>>(col, val, out, n_nodes);
    }
}

// round 12
// speedup vs baseline: 1.6038x; 1.1544x over previous
#include <cuda_runtime.h>
#include <cuda_fp16.h>
#include <cuda_bf16.h>

// out[row[e]] += values[e] * x[col[e]],  row sorted ascending.
// E = 1.6M, N = 100k, D = 64.
//
// Edge-balanced formulation (no row_ptr, no per-row loops):
//   - warp = 4 groups x 8 lanes; group owns CHUNK=16 CONSECUTIVE edges.
//   - lane fl owns fp16 feats [8*fl, 8*fl+8): one uint4 (16B) gather per edge,
//     8 lanes -> the full 128B fp16 row, exactly one L2 line per edge.
//   - fully unrolled 16-step loop: perfect load balance, no remainder chains.
//   - row boundary inside chunk (row sorted) -> flush partial sum via
//     PREDICATED red.global.add.v4.f32 (no branches); always flush at step 15.
// Prep (1 fused kernel): convert x -> fp16 table + zero-init out.

#define N_NODES 100000
#define D_FEAT 64
#define CHUNK 16

__device__ __align__(256) __half g_x_half[(size_t)N_NODES * D_FEAT];

__global__ void __launch_bounds__(256) fused_prep_kernel(
    const float* __restrict__ x, int n4,   // convert job: n4 = floats/4
    float* __restrict__ out, int n_out4,   // zero job: out_size/4
    int conv_blocks)
{
    if ((int)blockIdx.x < conv_blocks) {
        int i = blockIdx.x * blockDim.x + threadIdx.x;
        if (i >= n4) return;
        float4 f = __ldg(&((const float4*)x)[i]);
        __half2 h0 = __floats2half2_rn(f.x, f.y);
        __half2 h1 = __floats2half2_rn(f.z, f.w);
        uint2 packed;
        packed.x = *(unsigned*)&h0;
        packed.y = *(unsigned*)&h1;
        ((uint2*)g_x_half)[i] = packed;
    } else {
        int i = (blockIdx.x - conv_blocks) * blockDim.x + threadIdx.x;
        if (i >= n_out4) return;
        ((float4*)out)[i] = make_float4(0.f, 0.f, 0.f, 0.f);
    }
}

__device__ __forceinline__ void red_add_v4(float* addr, float a, float b,
                                           float c, float d, int pred) {
    asm volatile(
        "{\n\t"
        ".reg .pred p;\n\t"
        "setp.ne.s32 p, %0, 0;\n\t"
        "@p red.global.add.v4.f32 [%1], {%2, %3, %4, %5};\n\t"
        "}" :: "r"(pred), "l"(addr), "f"(a), "f"(b), "f"(c), "f"(d) : "memory");
}

__global__ void __launch_bounds__(256, 4) spmm_edge_chunk_kernel(
    const int* __restrict__ row,
    const int* __restrict__ col,
    const float* __restrict__ val,
    float* __restrict__ out,
    int n_edges)
{
    int gwarp = (blockIdx.x * blockDim.x + threadIdx.x) >> 5;
    int lane  = threadIdx.x & 31;
    int grp   = lane >> 3;          // which 16-edge chunk of this warp
    int fl    = lane & 7;           // owns fp16 feats [8*fl, 8*fl+8)

    long base = ((long)gwarp * 4 + grp) * CHUNK;
    if (base >= n_edges) return;

    const uint4* __restrict__ xq = (const uint4*)g_x_half;  // 8 uint4 per row

    float acc[8];
    #pragma unroll
    for (int k = 0; k < 8; ++k) acc[k] = 0.f;

    int last = n_edges - 1;
    int r_cur = __ldg(&row[min((int)base, last)]);

    #pragma unroll
    for (int j = 0; j < CHUNK; ++j) {
        int idx  = (int)base + j;
        int idxc = min(idx, last);
        int   c = __ldg(&col[idxc]);
        float v = (idx <= last) ? __ldg(&val[idxc]) : 0.f;   // OOB contributes 0
        int r_next = __ldg(&row[min(idx + 1, last)]);

        uint4 raw = __ldg(&xq[(size_t)c * (D_FEAT / 8) + fl]);  // 128B/edge line
        const __half2* hp = reinterpret_cast<const __half2*>(&raw);
        #pragma unroll
        for (int k = 0; k < 4; ++k) {
            float2 f = __half22float2(hp[k]);
            acc[2 * k]     = fmaf(v, f.x, acc[2 * k]);
            acc[2 * k + 1] = fmaf(v, f.y, acc[2 * k + 1]);
        }

        // flush after edge j if the segment ends here (row change / chunk end)
        int flush = (j == CHUNK - 1) || (r_next != r_cur) || (idx >= last);
        float* dst = out + (size_t)r_cur * D_FEAT + fl * 8;
        red_add_v4(dst,     acc[0], acc[1], acc[2], acc[3], flush);
        red_add_v4(dst + 4, acc[4], acc[5], acc[6], acc[7], flush);
        #pragma unroll
        for (int k = 0; k < 8; ++k) acc[k] = flush ? 0.f : acc[k];  // SEL, no branch
        r_cur = r_next;
    }
}

extern "C" void kernel_launch(void* const* d_in, const int* in_sizes, int n_in,
                              void* d_out, int out_size) {
    const int*   row = (const int*)d_in[0];
    const int*   col = (const int*)d_in[1];
    const float* val = (const float*)d_in[2];
    const float* x   = (const float*)d_in[3];
    float*       out = (float*)d_out;

    int n_edges = in_sizes[0];
    int n_x     = in_sizes[3];

    {
        int threads = 256;
        int n4 = n_x / 4;
        int n_out4 = out_size / 4;
        int conv_blocks = (n4 + threads - 1) / threads;
        int zero_blocks = (n_out4 + threads - 1) / threads;
        fused_prep_kernel<<<conv_blocks + zero_blocks, threads>>>(
            x, n4, out, n_out4, conv_blocks);
    }
    {
        int threads = 256;  // 8 warps/block; warp covers 4*CHUNK = 64 edges
        long chunks = ((long)n_edges + CHUNK - 1) / CHUNK;      // 8-lane groups
        long warps  = (chunks + 3) / 4;
        int blocks  = (int)((warps * 32 + threads - 1) / threads);
        spmm_edge_chunk_kernel<<<blocks, threads>>>(row, col, val, out, n_edges);
    }
}